// round 14
// baseline (speedup 1.0000x reference)
#include <cuda_runtime.h>
#include <cuda_fp16.h>
#include <math.h>
#include <stdint.h>

#define SEQ 1024
#define DIM 1024
#define NB  4
#define NHEAD 16
#define HD  64

enum { EPI_BIAS=1, EPI_BIAS_GELU=2 };

// ---------------- scratch (no allocations allowed) ----------------
__device__ float  g_t [(size_t)NB*SEQ*DIM];
__device__ float  g_x1[(size_t)NB*SEQ*DIM];
__device__ float  g_x2[(size_t)NB*SEQ*DIM];
__device__ __half g_qkvh[(size_t)NB*SEQ*3*DIM];
__device__ __half g_abufh[(size_t)NB*SEQ*DIM];
__device__ __half g_xh [(size_t)NB*SEQ*DIM];
__device__ __half g_ctxh[(size_t)NB*SEQ*DIM];
__device__ __half g_x1h[(size_t)NB*SEQ*DIM];
__device__ __half g_x2h[(size_t)NB*SEQ*DIM];
__device__ __half g_qh [(size_t)NB*SEQ*DIM];
__device__ __half g_kvh[(size_t)NB*SEQ*2*DIM];
__device__ __half g_hh [(size_t)NB*SEQ*4*DIM];
__device__ __half g_wth[(size_t)16*1024*1024];   // 32MB transposed half weights

__device__ __forceinline__ float gelu_tanh(float v){
    float u = 0.7978845608028654f * (v + 0.044715f * v * v * v);
    return 0.5f * v * (1.0f + tanhf(u));
}

#define CP_ASYNC16(s, g)  asm volatile("cp.async.cg.shared.global [%0], [%1], 16;" :: "r"(s), "l"(__cvta_generic_to_global(g)))
#define CP_COMMIT()       asm volatile("cp.async.commit_group;")
#define CP_WAIT(n)        asm volatile("cp.async.wait_group %0;" :: "n"(n))

#define LDSM_X4(r0,r1,r2,r3,addr) \
    asm volatile("ldmatrix.sync.aligned.m8n8.x4.shared.b16 {%0,%1,%2,%3}, [%4];" \
                 : "=r"(r0),"=r"(r1),"=r"(r2),"=r"(r3) : "r"(addr))
#define LDSM_X4T(r0,r1,r2,r3,addr) \
    asm volatile("ldmatrix.sync.aligned.m8n8.x4.trans.shared.b16 {%0,%1,%2,%3}, [%4];" \
                 : "=r"(r0),"=r"(r1),"=r"(r2),"=r"(r3) : "r"(addr))

__device__ __forceinline__ uint32_t smem_u32(const void* p) {
    uint32_t a;
    asm("{ .reg .u64 t; cvta.to.shared.u64 t, %1; cvt.u32.u64 %0, t; }" : "=r"(a) : "l"(p));
    return a;
}
__device__ __forceinline__ uint32_t f2h2(float lo, float hi) {
    uint32_t r;
    asm("cvt.rn.f16x2.f32 %0, %1, %2;" : "=r"(r) : "f"(hi), "f"(lo));
    return r;
}
__device__ __forceinline__ void mma_f16(float* d, const uint32_t* a, const uint32_t* b) {
    asm volatile(
        "mma.sync.aligned.m16n8k16.row.col.f32.f16.f16.f32 "
        "{%0,%1,%2,%3}, {%4,%5,%6,%7}, {%8,%9}, {%0,%1,%2,%3};"
        : "+f"(d[0]), "+f"(d[1]), "+f"(d[2]), "+f"(d[3])
        : "r"(a[0]), "r"(a[1]), "r"(a[2]), "r"(a[3]), "r"(b[0]), "r"(b[1]));
}

// ---------------- fp16 ldmatrix GEMM: 128x64 tile, 128 thr, 4 CTAs/SM ------
// C[M,N] = epi( A[M,K] * B^T )  A:[M,K] half K-major, B:[N,K] half K-major.
// 4 warps 2m x 2n; warp tile 64x32 (identical per-warp inner loop as before,
// but 4 independent barrier groups per SM decorrelate LDSM-stall phases).
template<int EPI, bool OUTH>
__global__ void __launch_bounds__(128, 4) gemm_mma(
    const __half* __restrict__ A, const __half* __restrict__ B,
    const float* __restrict__ bias, float* __restrict__ C, __half* __restrict__ Ch,
    int K, int lda, int ldb, int ldc)
{
    constexpr int BM = 128, BN = 64, BK = 32;
    constexpr int AST = 40;
    constexpr int SA = BM * AST, SB = BN * AST, STG = SA + SB;

    extern __shared__ __half smh[];
    const uint32_t sbase = smem_u32(smh);

    const int tid = threadIdx.x;
    const int row0 = blockIdx.y * BM;
    const int col0 = blockIdx.x * BN;
    const int wid = tid >> 5, lane = tid & 31;
    const int g = lane >> 2, tg = lane & 3;
    const int wm = (wid & 1) * 64;
    const int wn = (wid >> 1) * 32;

    float acc[4][4][4];
    #pragma unroll
    for (int mt = 0; mt < 4; mt++)
        #pragma unroll
        for (int nt = 0; nt < 4; nt++)
            #pragma unroll
            for (int i = 0; i < 4; i++) acc[mt][nt][i] = 0.f;

    auto load_stage = [&](int step) {
        int st = step % 3;
        long k0 = (long)step * BK;
        uint32_t as = sbase + (uint32_t)(st*STG)*2u;
        uint32_t bs = as + (uint32_t)SA*2u;
        #pragma unroll
        for (int i = 0; i < 4; i++) {               // A: 128 rows x 4 chunks
            int c = tid + i*128;
            int r = c >> 2, kc = c & 3;
            CP_ASYNC16(as + (uint32_t)(r*AST + kc*8)*2,
                       A + (long)(row0 + r)*lda + k0 + kc*8);
        }
        #pragma unroll
        for (int i = 0; i < 2; i++) {               // B: 64 rows x 4 chunks
            int c = tid + i*128;
            int r = c >> 2, kc = c & 3;
            CP_ASYNC16(bs + (uint32_t)(r*AST + kc*8)*2,
                       B + (long)(col0 + r)*ldb + k0 + kc*8);
        }
        CP_COMMIT();
    };

    const int nsteps = K / BK;
    load_stage(0);
    load_stage(1);

    const int a_r = lane & 15, a_c8 = (lane >> 4) << 3;
    const int b_r = ((lane >> 4) << 3) + (lane & 7);
    const int b_c8 = ((lane >> 3) & 1) << 3;

    for (int i = 0; i < nsteps; i++) {
        if (i + 1 < nsteps) { CP_WAIT(1); } else { CP_WAIT(0); }
        __syncthreads();
        if (i + 2 < nsteps) load_stage(i + 2);

        uint32_t as = sbase + (uint32_t)((i % 3)*STG)*2u;
        uint32_t bs = as + (uint32_t)SA*2u;

        #pragma unroll
        for (int kb = 0; kb < 2; kb++) {
            int kk = kb * 16;
            uint32_t af[4][4], bf[4][2];
            #pragma unroll
            for (int mt = 0; mt < 4; mt++) {
                uint32_t ad = as + (uint32_t)((wm + mt*16 + a_r)*AST + kk + a_c8)*2;
                LDSM_X4(af[mt][0], af[mt][1], af[mt][2], af[mt][3], ad);
            }
            #pragma unroll
            for (int p = 0; p < 2; p++) {
                uint32_t bd = bs + (uint32_t)((wn + p*16 + b_r)*AST + kk + b_c8)*2;
                LDSM_X4(bf[2*p][0], bf[2*p][1], bf[2*p+1][0], bf[2*p+1][1], bd);
            }
            #pragma unroll
            for (int mt = 0; mt < 4; mt++)
                #pragma unroll
                for (int nt = 0; nt < 4; nt++)
                    mma_f16(acc[mt][nt], af[mt], bf[nt]);
        }
    }

    #pragma unroll
    for (int mt = 0; mt < 4; mt++) {
        #pragma unroll
        for (int nt = 0; nt < 4; nt++) {
            int Rg = row0 + wm + mt*16 + g;
            int cg = col0 + wn + nt*8 + 2*tg;
            #pragma unroll
            for (int half_i = 0; half_i < 2; half_i++) {
                int r = Rg + half_i*8;
                float v0 = acc[mt][nt][half_i*2 + 0] + bias[cg];
                float v1 = acc[mt][nt][half_i*2 + 1] + bias[cg+1];
                if (EPI == EPI_BIAS_GELU) { v0 = gelu_tanh(v0); v1 = gelu_tanh(v1); }
                if (OUTH) {
                    *(uint32_t*)&Ch[(long)r*ldc + cg] = f2h2(v0, v1);
                } else {
                    *(float2*)&C[(long)r*ldc + cg] = make_float2(v0, v1);
                }
            }
        }
    }
}

// ---------------- fused flash attention: 128 threads, 64 Q rows/CTA ---------
__global__ void __launch_bounds__(128, 3) flash_attn(
    const __half* __restrict__ Q, const __half* __restrict__ K,
    const __half* __restrict__ V, __half* __restrict__ O,
    int ldq, int ldkv, int causal)
{
    constexpr int ST = 72;
    constexpr int QSZ = 64*ST;
    constexpr int KVSZ = 64*ST;
    constexpr int STGH = 2*KVSZ;
    extern __shared__ __half smh[];
    const uint32_t sbase = smem_u32(smh);

    const int tid = threadIdx.x;
    const int wid = tid >> 5, lane = tid & 31;
    const int g = lane >> 2, tg = lane & 3;
    const int qt = causal ? (int)(gridDim.x - 1 - blockIdx.x) : (int)blockIdx.x;
    const int bh = blockIdx.y, bb = bh >> 4, hh = bh & 15;
    const int wm = wid * 16;

    const __half* Qb = Q + (long)bb*SEQ*ldq  + hh*64 + (long)qt*64*ldq;
    const __half* Kb = K + (long)bb*SEQ*ldkv + hh*64;
    const __half* Vb = V + (long)bb*SEQ*ldkv + hh*64;
    __half*       Ob = O + (long)bb*SEQ*DIM  + hh*64 + (long)qt*64*DIM;

    #pragma unroll
    for (int i = 0; i < 4; i++) {
        int c = tid + i*128;
        int r = c >> 3, kc = c & 7;
        CP_ASYNC16(sbase + (uint32_t)(r*ST + kc*8)*2, Qb + (long)r*ldq + kc*8);
    }
    CP_COMMIT(); CP_WAIT(0);
    __syncthreads();

    const int a_r = lane & 15, a_c8 = (lane >> 4) << 3;
    const int b_r = ((lane >> 4) << 3) + (lane & 7);
    const int b_c8 = ((lane >> 3) & 1) << 3;
    const int v_r = (((lane >> 3) & 1) << 3) + (lane & 7);
    const int v_c8 = (lane >> 4) << 3;

    uint32_t aq[4][4];
    #pragma unroll
    for (int kt = 0; kt < 4; kt++) {
        uint32_t ad = sbase + (uint32_t)((wm + a_r)*ST + kt*16 + a_c8)*2;
        LDSM_X4(aq[kt][0], aq[kt][1], aq[kt][2], aq[kt][3], ad);
    }
    __syncthreads();

    float acc_o[8][4];
    #pragma unroll
    for (int nt = 0; nt < 8; nt++)
        #pragma unroll
        for (int i = 0; i < 4; i++) acc_o[nt][i] = 0.f;
    float m0 = -1e30f, m1 = -1e30f, l0 = 0.f, l1 = 0.f;

    const int ntiles = causal ? (qt + 1) : (SEQ/64);
    const int rowg0 = qt*64 + wm + g;
    const int rowg1 = rowg0 + 8;

    auto load_kv = [&](int j) {
        uint32_t st = sbase + (uint32_t)(QSZ + (j % 3)*STGH)*2u;
        const __half* Kg = Kb + (long)j*64*ldkv;
        const __half* Vg = Vb + (long)j*64*ldkv;
        #pragma unroll
        for (int i = 0; i < 4; i++) {
            int c = tid + i*128;
            int r = c >> 3, kc = c & 7;
            CP_ASYNC16(st + (uint32_t)(r*ST + kc*8)*2, Kg + (long)r*ldkv + kc*8);
        }
        uint32_t vs = st + (uint32_t)KVSZ*2u;
        #pragma unroll
        for (int i = 0; i < 4; i++) {
            int c = tid + i*128;
            int r = c >> 3, kc = c & 7;
            CP_ASYNC16(vs + (uint32_t)(r*ST + kc*8)*2, Vg + (long)r*ldkv + kc*8);
        }
        CP_COMMIT();
    };

    load_kv(0);
    if (ntiles > 1) load_kv(1);

    for (int j = 0; j < ntiles; j++) {
        if (j + 1 < ntiles) { CP_WAIT(1); } else { CP_WAIT(0); }
        __syncthreads();
        if (j + 2 < ntiles) load_kv(j + 2);

        uint32_t ks = sbase + (uint32_t)(QSZ + (j % 3)*STGH)*2u;
        uint32_t vs = ks + (uint32_t)KVSZ*2u;

        float s[8][4];
        #pragma unroll
        for (int nt = 0; nt < 8; nt++)
            #pragma unroll
            for (int i = 0; i < 4; i++) s[nt][i] = 0.f;

        #pragma unroll
        for (int kt = 0; kt < 4; kt++) {
            int kk = kt*16;
            #pragma unroll
            for (int p = 0; p < 4; p++) {
                uint32_t bf[2][2];
                uint32_t bd = ks + (uint32_t)((p*16 + b_r)*ST + kk + b_c8)*2;
                LDSM_X4(bf[0][0], bf[0][1], bf[1][0], bf[1][1], bd);
                mma_f16(s[2*p  ], aq[kt], bf[0]);
                mma_f16(s[2*p+1], aq[kt], bf[1]);
            }
        }

        #pragma unroll
        for (int nt = 0; nt < 8; nt++)
            #pragma unroll
            for (int i = 0; i < 4; i++) s[nt][i] *= 0.125f;

        if (causal && j == qt) {
            int kbase = j*64;
            #pragma unroll
            for (int nt = 0; nt < 8; nt++) {
                int kg = kbase + nt*8 + 2*tg;
                if (kg     > rowg0) s[nt][0] = -1e30f;
                if (kg + 1 > rowg0) s[nt][1] = -1e30f;
                if (kg     > rowg1) s[nt][2] = -1e30f;
                if (kg + 1 > rowg1) s[nt][3] = -1e30f;
            }
        }

        float tm0 = -1e30f, tm1 = -1e30f;
        #pragma unroll
        for (int nt = 0; nt < 8; nt++) {
            tm0 = fmaxf(tm0, fmaxf(s[nt][0], s[nt][1]));
            tm1 = fmaxf(tm1, fmaxf(s[nt][2], s[nt][3]));
        }
        tm0 = fmaxf(tm0, __shfl_xor_sync(0xffffffffu, tm0, 1));
        tm0 = fmaxf(tm0, __shfl_xor_sync(0xffffffffu, tm0, 2));
        tm1 = fmaxf(tm1, __shfl_xor_sync(0xffffffffu, tm1, 1));
        tm1 = fmaxf(tm1, __shfl_xor_sync(0xffffffffu, tm1, 2));

        float mn0 = fmaxf(m0, tm0), mn1 = fmaxf(m1, tm1);
        float al0 = __expf(m0 - mn0), al1 = __expf(m1 - mn1);
        float ts0 = 0.f, ts1 = 0.f;
        #pragma unroll
        for (int nt = 0; nt < 8; nt++) {
            s[nt][0] = __expf(s[nt][0] - mn0);
            s[nt][1] = __expf(s[nt][1] - mn0);
            s[nt][2] = __expf(s[nt][2] - mn1);
            s[nt][3] = __expf(s[nt][3] - mn1);
            ts0 += s[nt][0] + s[nt][1];
            ts1 += s[nt][2] + s[nt][3];
        }
        ts0 += __shfl_xor_sync(0xffffffffu, ts0, 1);
        ts0 += __shfl_xor_sync(0xffffffffu, ts0, 2);
        ts1 += __shfl_xor_sync(0xffffffffu, ts1, 1);
        ts1 += __shfl_xor_sync(0xffffffffu, ts1, 2);

        l0 = l0*al0 + ts0;  l1 = l1*al1 + ts1;
        m0 = mn0;  m1 = mn1;

        #pragma unroll
        for (int nt = 0; nt < 8; nt++) {
            acc_o[nt][0] *= al0;  acc_o[nt][1] *= al0;
            acc_o[nt][2] *= al1;  acc_o[nt][3] *= al1;
        }

        #pragma unroll
        for (int kt = 0; kt < 4; kt++) {
            uint32_t ap[4];
            ap[0] = f2h2(s[2*kt  ][0], s[2*kt  ][1]);
            ap[1] = f2h2(s[2*kt  ][2], s[2*kt  ][3]);
            ap[2] = f2h2(s[2*kt+1][0], s[2*kt+1][1]);
            ap[3] = f2h2(s[2*kt+1][2], s[2*kt+1][3]);
            #pragma unroll
            for (int p = 0; p < 4; p++) {
                uint32_t bv[2][2];
                uint32_t vd = vs + (uint32_t)((kt*16 + v_r)*ST + p*16 + v_c8)*2;
                LDSM_X4T(bv[0][0], bv[0][1], bv[1][0], bv[1][1], vd);
                mma_f16(acc_o[2*p  ], ap, bv[0]);
                mma_f16(acc_o[2*p+1], ap, bv[1]);
            }
        }
    }

    float r0 = 1.f / l0, r1 = 1.f / l1;
    #pragma unroll
    for (int nt = 0; nt < 8; nt++) {
        int c = nt*8 + 2*tg;
        *(uint32_t*)&Ob[(long)(wm+g  )*DIM + c] = f2h2(acc_o[nt][0]*r0, acc_o[nt][1]*r0);
        *(uint32_t*)&Ob[(long)(wm+g+8)*DIM + c] = f2h2(acc_o[nt][2]*r1, acc_o[nt][3]*r1);
    }
}

// ---------------- merged weight transposes (7 segments, flat grid) ----------
__global__ void prep_weights(
    const float* w0, const float* w1, const float* w2, const float* w3,
    const float* w4, const float* w5, const float* w6,
    __half* o0, __half* o1, __half* o2, __half* o3,
    __half* o4, __half* o5, __half* o6)
{
    const int gx[7]  = {96, 32, 32, 64, 32, 128, 32};
    const int off[8] = {0, 3072, 4096, 5120, 7168, 8192, 12288, 16384};
    const int ldi[7] = {3072, 1024, 1024, 2048, 1024, 4096, 1024};
    const int ldo[7] = {1024, 1024, 1024, 1024, 1024, 1024, 4096};

    int bid = blockIdx.x;
    int seg = 0;
    #pragma unroll
    for (int s = 1; s < 7; s++) if (bid >= off[s]) seg = s;
    int lt = bid - off[seg];
    int bx = lt % gx[seg], by = lt / gx[seg];

    const float* in  = (seg==0)?w0:(seg==1)?w1:(seg==2)?w2:(seg==3)?w3:(seg==4)?w4:(seg==5)?w5:w6;
    __half*      out = (seg==0)?o0:(seg==1)?o1:(seg==2)?o2:(seg==3)?o3:(seg==4)?o4:(seg==5)?o5:o6;
    int ldin = ldi[seg], ldout = ldo[seg];

    __shared__ float t[32][33];
    int r0 = by*32, c0 = bx*32;
    int x = threadIdx.x, y = threadIdx.y;
    #pragma unroll
    for (int i = 0; i < 32; i += 8) t[y+i][x] = in[(long)(r0+y+i)*ldin + c0 + x];
    __syncthreads();
    #pragma unroll
    for (int i = 0; i < 32; i += 8)
        out[(long)(c0+y+i)*ldout + r0 + x] = __float2half(t[x][y+i]);
}

// ---------------- merged fp32 -> half convert (x and ctx) ----------------
__global__ void f2h_dual(const float* __restrict__ a, __half* __restrict__ ah,
                         const float* __restrict__ b, __half* __restrict__ bh, int n4)
{
    int i = blockIdx.x*blockDim.x + threadIdx.x;
    const float* in; __half* out;
    if (i < n4) { in = a; out = ah; }
    else        { in = b; out = bh; i -= n4; if (i >= n4) return; }
    float4 v = ((const float4*)in)[i];
    ((uint32_t*)out)[2*i    ] = f2h2(v.x, v.y);
    ((uint32_t*)out)[2*i + 1] = f2h2(v.z, v.w);
}

// ---------------- fused residual add + LayerNorm ----------------
__global__ void __launch_bounds__(256) add_ln(
    const float* __restrict__ x, const float* __restrict__ a,
    const float* __restrict__ g, const float* __restrict__ b,
    float* __restrict__ y, __half* __restrict__ yh)
{
    __shared__ float red[8];
    __shared__ float bc;
    long row = blockIdx.x;
    const float* xr = x + row * DIM;
    const float* ar = a + row * DIM;
    float* yr = y + row * DIM;
    int tid = threadIdx.x, lane = tid & 31, wid = tid >> 5;

    float v[4], s = 0.f;
    #pragma unroll
    for (int i = 0; i < 4; i++) { int c = tid + i*256; v[i] = xr[c] + ar[c]; s += v[i]; }
    #pragma unroll
    for (int o = 16; o > 0; o >>= 1) s += __shfl_xor_sync(0xffffffffu, s, o);
    if (lane == 0) red[wid] = s;
    __syncthreads();
    if (tid == 0) {
        float t = 0.f;
        #pragma unroll
        for (int i = 0; i < 8; i++) t += red[i];
        bc = t * (1.0f / DIM);
    }
    __syncthreads();
    float mu = bc;

    float q = 0.f;
    #pragma unroll
    for (int i = 0; i < 4; i++) { float d = v[i] - mu; q += d * d; }
    #pragma unroll
    for (int o = 16; o > 0; o >>= 1) q += __shfl_xor_sync(0xffffffffu, q, o);
    __syncthreads();
    if (lane == 0) red[wid] = q;
    __syncthreads();
    if (tid == 0) {
        float t = 0.f;
        #pragma unroll
        for (int i = 0; i < 8; i++) t += red[i];
        bc = rsqrtf(t * (1.0f / DIM) + 1e-5f);
    }
    __syncthreads();
    float inv = bc;
    #pragma unroll
    for (int i = 0; i < 4; i++) {
        int c = tid + i*256;
        float o = (v[i] - mu) * inv * g[c] + b[c];
        yr[c] = o;
        if (yh) yh[row*DIM + c] = __float2half(o);
    }
}

// ---------------- host orchestration (two-stream graph) ----------------
extern "C" void kernel_launch(void* const* d_in, const int* in_sizes, int n_in,
                              void* d_out, int out_size)
{
    const float* x            = (const float*)d_in[0];
    const float* ctx          = (const float*)d_in[1];
    const float* c_attn_w     = (const float*)d_in[2];
    const float* c_attn_b     = (const float*)d_in[3];
    const float* self_proj_w  = (const float*)d_in[4];
    const float* self_proj_b  = (const float*)d_in[5];
    const float* q_w          = (const float*)d_in[6];
    const float* q_b          = (const float*)d_in[7];
    const float* kv_w         = (const float*)d_in[8];
    const float* kv_b         = (const float*)d_in[9];
    const float* cross_proj_w = (const float*)d_in[10];
    const float* cross_proj_b = (const float*)d_in[11];
    const float* fc_w         = (const float*)d_in[12];
    const float* fc_b         = (const float*)d_in[13];
    const float* mlp_proj_w   = (const float*)d_in[14];
    const float* mlp_proj_b   = (const float*)d_in[15];
    const float* ln1_g        = (const float*)d_in[16];
    const float* ln1_b        = (const float*)d_in[17];
    const float* ln2_g        = (const float*)d_in[18];
    const float* ln2_b        = (const float*)d_in[19];
    const float* ln3_g        = (const float*)d_in[20];
    const float* ln3_b        = (const float*)d_in[21];
    float* out = (float*)d_out;

    float *t, *x1, *x2;
    __half *qkvh, *abufh, *xh, *ctxh, *x1h, *x2h, *qh, *kvh, *hh, *wth;
    cudaGetSymbolAddress((void**)&t,     g_t);
    cudaGetSymbolAddress((void**)&x1,    g_x1);
    cudaGetSymbolAddress((void**)&x2,    g_x2);
    cudaGetSymbolAddress((void**)&qkvh,  g_qkvh);
    cudaGetSymbolAddress((void**)&abufh, g_abufh);
    cudaGetSymbolAddress((void**)&xh,    g_xh);
    cudaGetSymbolAddress((void**)&ctxh,  g_ctxh);
    cudaGetSymbolAddress((void**)&x1h,   g_x1h);
    cudaGetSymbolAddress((void**)&x2h,   g_x2h);
    cudaGetSymbolAddress((void**)&qh,    g_qh);
    cudaGetSymbolAddress((void**)&kvh,   g_kvh);
    cudaGetSymbolAddress((void**)&hh,    g_hh);
    cudaGetSymbolAddress((void**)&wth,   g_wth);

    __half* cattnT = wth;                        // [3072,1024]
    __half* selfT  = wth +  3l*1024*1024;
    __half* qT     = wth +  4l*1024*1024;
    __half* kvT    = wth +  5l*1024*1024;        // [2048,1024]
    __half* crossT = wth +  7l*1024*1024;
    __half* fcT    = wth +  8l*1024*1024;        // [4096,1024]
    __half* mlpT   = wth + 12l*1024*1024;        // [1024,4096]

    const int SMG = (128*40 + 64*40) * 3 * 2;           // 46080 B (3 stages)
    const int SMF = (64*72 + 3*(2*64*72)) * 2;          // 64512 B (Q + 3 KV stages)

    static bool init_done = false;
    static cudaStream_t s2;
    static cudaEvent_t evStart, evF, evW, evKV;
    if (!init_done) {
        cudaFuncSetAttribute(gemm_mma<EPI_BIAS, true>,      cudaFuncAttributeMaxDynamicSharedMemorySize, SMG);
        cudaFuncSetAttribute(gemm_mma<EPI_BIAS, false>,     cudaFuncAttributeMaxDynamicSharedMemorySize, SMG);
        cudaFuncSetAttribute(gemm_mma<EPI_BIAS_GELU, true>, cudaFuncAttributeMaxDynamicSharedMemorySize, SMG);
        cudaFuncSetAttribute(flash_attn, cudaFuncAttributeMaxDynamicSharedMemorySize, SMF);
        cudaStreamCreateWithFlags(&s2, cudaStreamNonBlocking);
        cudaEventCreateWithFlags(&evStart, cudaEventDisableTiming);
        cudaEventCreateWithFlags(&evF,     cudaEventDisableTiming);
        cudaEventCreateWithFlags(&evW,     cudaEventDisableTiming);
        cudaEventCreateWithFlags(&evKV,    cudaEventDisableTiming);
        init_done = true;
    }

    const int M = NB * SEQ;                  // 4096

    // ---- fork: side stream does weight prep, then the kv projection ----
    cudaEventRecord(evStart, 0);
    cudaStreamWaitEvent(s2, evStart, 0);

    // main: input converts (xh, ctxh)
    f2h_dual<<<8192, 256>>>(x, xh, ctx, ctxh, M*DIM/4);
    cudaEventRecord(evF, 0);

    // side: all weight transposes
    prep_weights<<<16384, dim3(32, 8), 0, s2>>>(
        c_attn_w, self_proj_w, q_w, kv_w, cross_proj_w, fc_w, mlp_proj_w,
        cattnT, selfT, qT, kvT, crossT, fcT, mlpT);
    cudaEventRecord(evW, s2);

    // side: kv = ctx @ kv_w + b  (needs ctxh from main + kvT local)
    cudaStreamWaitEvent(s2, evF, 0);
    gemm_mma<EPI_BIAS, true><<<dim3(32, 32), 128, SMG, s2>>>(
        ctxh, kvT, kv_b, nullptr, kvh, DIM, DIM, DIM, 2*DIM);
    cudaEventRecord(evKV, s2);

    // main waits for weights (cattnT) before qkv
    cudaStreamWaitEvent(0, evW, 0);

    // 1. qkv = x @ c_attn_w + b   (half out)
    gemm_mma<EPI_BIAS, true><<<dim3(48, 32), 128, SMG>>>(
        xh, cattnT, c_attn_b, nullptr, qkvh, DIM, DIM, DIM, 3*DIM);

    // 2-4. fused causal self-attention -> abufh
    flash_attn<<<dim3(16, NB*NHEAD), 128, SMF>>>(
        qkvh, qkvh + DIM, qkvh + 2*DIM, abufh, 3*DIM, 3*DIM, 1);

    // 5. t = a @ self_proj_w + b  (fp32 out)
    gemm_mma<EPI_BIAS, false><<<dim3(16, 32), 128, SMG>>>(
        abufh, selfT, self_proj_b, t, nullptr, DIM, DIM, DIM, DIM);

    // 6. x1 = LN(x + t)  (+ half copy)
    add_ln<<<M, 256>>>(x, t, ln1_g, ln1_b, x1, x1h);

    // 7. q = x1 @ q_w + b  (half out)
    gemm_mma<EPI_BIAS, true><<<dim3(16, 32), 128, SMG>>>(
        x1h, qT, q_b, nullptr, qh, DIM, DIM, DIM, DIM);

    // join: cross-attention needs kv from side stream
    cudaStreamWaitEvent(0, evKV, 0);

    // 9-11. fused cross-attention -> abufh
    flash_attn<<<dim3(16, NB*NHEAD), 128, SMF>>>(
        qh, kvh, kvh + DIM, abufh, DIM, 2*DIM, 0);

    // 12. t = a @ cross_proj_w + b  (fp32 out)
    gemm_mma<EPI_BIAS, false><<<dim3(16, 32), 128, SMG>>>(
        abufh, crossT, cross_proj_b, t, nullptr, DIM, DIM, DIM, DIM);

    // 13. x2 = LN(x1 + t)  (+ half copy)
    add_ln<<<M, 256>>>(x1, t, ln2_g, ln2_b, x2, x2h);

    // 14. h = gelu(x2 @ fc_w + b)  (half out)
    gemm_mma<EPI_BIAS_GELU, true><<<dim3(64, 32), 128, SMG>>>(
        x2h, fcT, fc_b, nullptr, hh, DIM, DIM, DIM, 4*DIM);

    // 15. t = h @ mlp_proj_w + b  (fp32 out)
    gemm_mma<EPI_BIAS, false><<<dim3(16, 32), 128, SMG>>>(
        hh, mlpT, mlp_proj_b, t, nullptr, 4*DIM, 4*DIM, 4*DIM, DIM);

    // 16. out = LN(x2 + t)
    add_ln<<<M, 256>>>(x2, t, ln3_g, ln3_b, out, nullptr);
}

// round 15
// speedup vs baseline: 1.1123x; 1.1123x over previous
#include <cuda_runtime.h>
#include <cuda_fp16.h>
#include <math.h>
#include <stdint.h>

#define SEQ 1024
#define DIM 1024
#define NB  4
#define NHEAD 16
#define HD  64

enum { EPI_BIAS=1, EPI_BIAS_GELU=2 };

// ---------------- scratch (no allocations allowed) ----------------
__device__ float  g_t [(size_t)NB*SEQ*DIM];
__device__ float  g_x1[(size_t)NB*SEQ*DIM];
__device__ float  g_x2[(size_t)NB*SEQ*DIM];
__device__ __half g_qkvh[(size_t)NB*SEQ*3*DIM];
__device__ __half g_abufh[(size_t)NB*SEQ*DIM];
__device__ __half g_xh [(size_t)NB*SEQ*DIM];
__device__ __half g_ctxh[(size_t)NB*SEQ*DIM];
__device__ __half g_x1h[(size_t)NB*SEQ*DIM];
__device__ __half g_x2h[(size_t)NB*SEQ*DIM];
__device__ __half g_qh [(size_t)NB*SEQ*DIM];
__device__ __half g_kvh[(size_t)NB*SEQ*2*DIM];
__device__ __half g_hh [(size_t)NB*SEQ*4*DIM];
__device__ __half g_wth[(size_t)16*1024*1024];   // 32MB transposed half weights

__device__ __forceinline__ float gelu_tanh(float v){
    float u = 0.7978845608028654f * (v + 0.044715f * v * v * v);
    return 0.5f * v * (1.0f + tanhf(u));
}

#define CP_ASYNC16(s, g)  asm volatile("cp.async.cg.shared.global [%0], [%1], 16;" :: "r"(s), "l"(__cvta_generic_to_global(g)))
#define CP_COMMIT()       asm volatile("cp.async.commit_group;")
#define CP_WAIT(n)        asm volatile("cp.async.wait_group %0;" :: "n"(n))

#define LDSM_X4(r0,r1,r2,r3,addr) \
    asm volatile("ldmatrix.sync.aligned.m8n8.x4.shared.b16 {%0,%1,%2,%3}, [%4];" \
                 : "=r"(r0),"=r"(r1),"=r"(r2),"=r"(r3) : "r"(addr))
#define LDSM_X4T(r0,r1,r2,r3,addr) \
    asm volatile("ldmatrix.sync.aligned.m8n8.x4.trans.shared.b16 {%0,%1,%2,%3}, [%4];" \
                 : "=r"(r0),"=r"(r1),"=r"(r2),"=r"(r3) : "r"(addr))

__device__ __forceinline__ uint32_t smem_u32(const void* p) {
    uint32_t a;
    asm("{ .reg .u64 t; cvta.to.shared.u64 t, %1; cvt.u32.u64 %0, t; }" : "=r"(a) : "l"(p));
    return a;
}
__device__ __forceinline__ uint32_t f2h2(float lo, float hi) {
    uint32_t r;
    asm("cvt.rn.f16x2.f32 %0, %1, %2;" : "=r"(r) : "f"(hi), "f"(lo));
    return r;
}
__device__ __forceinline__ void mma_f16(float* d, const uint32_t* a, const uint32_t* b) {
    asm volatile(
        "mma.sync.aligned.m16n8k16.row.col.f32.f16.f16.f32 "
        "{%0,%1,%2,%3}, {%4,%5,%6,%7}, {%8,%9}, {%0,%1,%2,%3};"
        : "+f"(d[0]), "+f"(d[1]), "+f"(d[2]), "+f"(d[3])
        : "r"(a[0]), "r"(a[1]), "r"(a[2]), "r"(a[3]), "r"(b[0]), "r"(b[1]));
}

// ---------------- fp16 ldmatrix GEMM: 128x128 tile, 128 thr, 64x64 warp tile
// C[M,N] = epi( A[M,K] * B^T )  A:[M,K] half K-major, B:[N,K] half K-major.
// 4 warps 2m x 2n; warp tile 64x64: 8 LDSM.x4 per 32 MMA (1.56x less smem
// traffic per FLOP than 64x32) with deep per-warp MMA ILP. 2 CTAs/SM.
template<int EPI, bool OUTH>
__global__ void __launch_bounds__(128, 2) gemm_mma(
    const __half* __restrict__ A, const __half* __restrict__ B,
    const float* __restrict__ bias, float* __restrict__ C, __half* __restrict__ Ch,
    int K, int lda, int ldb, int ldc)
{
    constexpr int BM = 128, BN = 128, BK = 32;
    constexpr int AST = 40;
    constexpr int SA = BM * AST, SB = BN * AST, STG = SA + SB;

    extern __shared__ __half smh[];
    const uint32_t sbase = smem_u32(smh);

    const int tid = threadIdx.x;
    const int row0 = blockIdx.y * BM;
    const int col0 = blockIdx.x * BN;
    const int wid = tid >> 5, lane = tid & 31;
    const int g = lane >> 2, tg = lane & 3;
    const int wm = (wid & 1) * 64;
    const int wn = (wid >> 1) * 64;

    float acc[4][8][4];
    #pragma unroll
    for (int mt = 0; mt < 4; mt++)
        #pragma unroll
        for (int nt = 0; nt < 8; nt++)
            #pragma unroll
            for (int i = 0; i < 4; i++) acc[mt][nt][i] = 0.f;

    auto load_stage = [&](int step) {
        int st = step % 3;
        long k0 = (long)step * BK;
        uint32_t as = sbase + (uint32_t)(st*STG)*2u;
        uint32_t bs = as + (uint32_t)SA*2u;
        #pragma unroll
        for (int i = 0; i < 4; i++) {               // A: 128 rows x 4 chunks
            int c = tid + i*128;
            int r = c >> 2, kc = c & 3;
            CP_ASYNC16(as + (uint32_t)(r*AST + kc*8)*2,
                       A + (long)(row0 + r)*lda + k0 + kc*8);
        }
        #pragma unroll
        for (int i = 0; i < 4; i++) {               // B: 128 rows x 4 chunks
            int c = tid + i*128;
            int r = c >> 2, kc = c & 3;
            CP_ASYNC16(bs + (uint32_t)(r*AST + kc*8)*2,
                       B + (long)(col0 + r)*ldb + k0 + kc*8);
        }
        CP_COMMIT();
    };

    const int nsteps = K / BK;
    load_stage(0);
    load_stage(1);

    const int a_r = lane & 15, a_c8 = (lane >> 4) << 3;
    const int b_r = ((lane >> 4) << 3) + (lane & 7);
    const int b_c8 = ((lane >> 3) & 1) << 3;

    for (int i = 0; i < nsteps; i++) {
        if (i + 1 < nsteps) { CP_WAIT(1); } else { CP_WAIT(0); }
        __syncthreads();
        if (i + 2 < nsteps) load_stage(i + 2);

        uint32_t as = sbase + (uint32_t)((i % 3)*STG)*2u;
        uint32_t bs = as + (uint32_t)SA*2u;

        #pragma unroll
        for (int kb = 0; kb < 2; kb++) {
            int kk = kb * 16;
            uint32_t af[4][4], bf[8][2];
            #pragma unroll
            for (int mt = 0; mt < 4; mt++) {
                uint32_t ad = as + (uint32_t)((wm + mt*16 + a_r)*AST + kk + a_c8)*2;
                LDSM_X4(af[mt][0], af[mt][1], af[mt][2], af[mt][3], ad);
            }
            #pragma unroll
            for (int p = 0; p < 4; p++) {
                uint32_t bd = bs + (uint32_t)((wn + p*16 + b_r)*AST + kk + b_c8)*2;
                LDSM_X4(bf[2*p][0], bf[2*p][1], bf[2*p+1][0], bf[2*p+1][1], bd);
            }
            #pragma unroll
            for (int mt = 0; mt < 4; mt++)
                #pragma unroll
                for (int nt = 0; nt < 8; nt++)
                    mma_f16(acc[mt][nt], af[mt], bf[nt]);
        }
    }

    #pragma unroll
    for (int mt = 0; mt < 4; mt++) {
        #pragma unroll
        for (int nt = 0; nt < 8; nt++) {
            int Rg = row0 + wm + mt*16 + g;
            int cg = col0 + wn + nt*8 + 2*tg;
            #pragma unroll
            for (int half_i = 0; half_i < 2; half_i++) {
                int r = Rg + half_i*8;
                float v0 = acc[mt][nt][half_i*2 + 0] + bias[cg];
                float v1 = acc[mt][nt][half_i*2 + 1] + bias[cg+1];
                if (EPI == EPI_BIAS_GELU) { v0 = gelu_tanh(v0); v1 = gelu_tanh(v1); }
                if (OUTH) {
                    *(uint32_t*)&Ch[(long)r*ldc + cg] = f2h2(v0, v1);
                } else {
                    *(float2*)&C[(long)r*ldc + cg] = make_float2(v0, v1);
                }
            }
        }
    }
}

// ---------------- fused flash attention: 128 threads, 64 Q rows/CTA ---------
__global__ void __launch_bounds__(128, 3) flash_attn(
    const __half* __restrict__ Q, const __half* __restrict__ K,
    const __half* __restrict__ V, __half* __restrict__ O,
    int ldq, int ldkv, int causal)
{
    constexpr int ST = 72;
    constexpr int QSZ = 64*ST;
    constexpr int KVSZ = 64*ST;
    constexpr int STGH = 2*KVSZ;
    extern __shared__ __half smh[];
    const uint32_t sbase = smem_u32(smh);

    const int tid = threadIdx.x;
    const int wid = tid >> 5, lane = tid & 31;
    const int g = lane >> 2, tg = lane & 3;
    const int qt = causal ? (int)(gridDim.x - 1 - blockIdx.x) : (int)blockIdx.x;
    const int bh = blockIdx.y, bb = bh >> 4, hh = bh & 15;
    const int wm = wid * 16;

    const __half* Qb = Q + (long)bb*SEQ*ldq  + hh*64 + (long)qt*64*ldq;
    const __half* Kb = K + (long)bb*SEQ*ldkv + hh*64;
    const __half* Vb = V + (long)bb*SEQ*ldkv + hh*64;
    __half*       Ob = O + (long)bb*SEQ*DIM  + hh*64 + (long)qt*64*DIM;

    #pragma unroll
    for (int i = 0; i < 4; i++) {
        int c = tid + i*128;
        int r = c >> 3, kc = c & 7;
        CP_ASYNC16(sbase + (uint32_t)(r*ST + kc*8)*2, Qb + (long)r*ldq + kc*8);
    }
    CP_COMMIT(); CP_WAIT(0);
    __syncthreads();

    const int a_r = lane & 15, a_c8 = (lane >> 4) << 3;
    const int b_r = ((lane >> 4) << 3) + (lane & 7);
    const int b_c8 = ((lane >> 3) & 1) << 3;
    const int v_r = (((lane >> 3) & 1) << 3) + (lane & 7);
    const int v_c8 = (lane >> 4) << 3;

    uint32_t aq[4][4];
    #pragma unroll
    for (int kt = 0; kt < 4; kt++) {
        uint32_t ad = sbase + (uint32_t)((wm + a_r)*ST + kt*16 + a_c8)*2;
        LDSM_X4(aq[kt][0], aq[kt][1], aq[kt][2], aq[kt][3], ad);
    }
    __syncthreads();

    float acc_o[8][4];
    #pragma unroll
    for (int nt = 0; nt < 8; nt++)
        #pragma unroll
        for (int i = 0; i < 4; i++) acc_o[nt][i] = 0.f;
    float m0 = -1e30f, m1 = -1e30f, l0 = 0.f, l1 = 0.f;

    const int ntiles = causal ? (qt + 1) : (SEQ/64);
    const int rowg0 = qt*64 + wm + g;
    const int rowg1 = rowg0 + 8;

    auto load_kv = [&](int j) {
        uint32_t st = sbase + (uint32_t)(QSZ + (j % 3)*STGH)*2u;
        const __half* Kg = Kb + (long)j*64*ldkv;
        const __half* Vg = Vb + (long)j*64*ldkv;
        #pragma unroll
        for (int i = 0; i < 4; i++) {
            int c = tid + i*128;
            int r = c >> 3, kc = c & 7;
            CP_ASYNC16(st + (uint32_t)(r*ST + kc*8)*2, Kg + (long)r*ldkv + kc*8);
        }
        uint32_t vs = st + (uint32_t)KVSZ*2u;
        #pragma unroll
        for (int i = 0; i < 4; i++) {
            int c = tid + i*128;
            int r = c >> 3, kc = c & 7;
            CP_ASYNC16(vs + (uint32_t)(r*ST + kc*8)*2, Vg + (long)r*ldkv + kc*8);
        }
        CP_COMMIT();
    };

    load_kv(0);
    if (ntiles > 1) load_kv(1);

    for (int j = 0; j < ntiles; j++) {
        if (j + 1 < ntiles) { CP_WAIT(1); } else { CP_WAIT(0); }
        __syncthreads();
        if (j + 2 < ntiles) load_kv(j + 2);

        uint32_t ks = sbase + (uint32_t)(QSZ + (j % 3)*STGH)*2u;
        uint32_t vs = ks + (uint32_t)KVSZ*2u;

        float s[8][4];
        #pragma unroll
        for (int nt = 0; nt < 8; nt++)
            #pragma unroll
            for (int i = 0; i < 4; i++) s[nt][i] = 0.f;

        #pragma unroll
        for (int kt = 0; kt < 4; kt++) {
            int kk = kt*16;
            #pragma unroll
            for (int p = 0; p < 4; p++) {
                uint32_t bf[2][2];
                uint32_t bd = ks + (uint32_t)((p*16 + b_r)*ST + kk + b_c8)*2;
                LDSM_X4(bf[0][0], bf[0][1], bf[1][0], bf[1][1], bd);
                mma_f16(s[2*p  ], aq[kt], bf[0]);
                mma_f16(s[2*p+1], aq[kt], bf[1]);
            }
        }

        #pragma unroll
        for (int nt = 0; nt < 8; nt++)
            #pragma unroll
            for (int i = 0; i < 4; i++) s[nt][i] *= 0.125f;

        if (causal && j == qt) {
            int kbase = j*64;
            #pragma unroll
            for (int nt = 0; nt < 8; nt++) {
                int kg = kbase + nt*8 + 2*tg;
                if (kg     > rowg0) s[nt][0] = -1e30f;
                if (kg + 1 > rowg0) s[nt][1] = -1e30f;
                if (kg     > rowg1) s[nt][2] = -1e30f;
                if (kg + 1 > rowg1) s[nt][3] = -1e30f;
            }
        }

        float tm0 = -1e30f, tm1 = -1e30f;
        #pragma unroll
        for (int nt = 0; nt < 8; nt++) {
            tm0 = fmaxf(tm0, fmaxf(s[nt][0], s[nt][1]));
            tm1 = fmaxf(tm1, fmaxf(s[nt][2], s[nt][3]));
        }
        tm0 = fmaxf(tm0, __shfl_xor_sync(0xffffffffu, tm0, 1));
        tm0 = fmaxf(tm0, __shfl_xor_sync(0xffffffffu, tm0, 2));
        tm1 = fmaxf(tm1, __shfl_xor_sync(0xffffffffu, tm1, 1));
        tm1 = fmaxf(tm1, __shfl_xor_sync(0xffffffffu, tm1, 2));

        float mn0 = fmaxf(m0, tm0), mn1 = fmaxf(m1, tm1);
        float al0 = __expf(m0 - mn0), al1 = __expf(m1 - mn1);
        float ts0 = 0.f, ts1 = 0.f;
        #pragma unroll
        for (int nt = 0; nt < 8; nt++) {
            s[nt][0] = __expf(s[nt][0] - mn0);
            s[nt][1] = __expf(s[nt][1] - mn0);
            s[nt][2] = __expf(s[nt][2] - mn1);
            s[nt][3] = __expf(s[nt][3] - mn1);
            ts0 += s[nt][0] + s[nt][1];
            ts1 += s[nt][2] + s[nt][3];
        }
        ts0 += __shfl_xor_sync(0xffffffffu, ts0, 1);
        ts0 += __shfl_xor_sync(0xffffffffu, ts0, 2);
        ts1 += __shfl_xor_sync(0xffffffffu, ts1, 1);
        ts1 += __shfl_xor_sync(0xffffffffu, ts1, 2);

        l0 = l0*al0 + ts0;  l1 = l1*al1 + ts1;
        m0 = mn0;  m1 = mn1;

        #pragma unroll
        for (int nt = 0; nt < 8; nt++) {
            acc_o[nt][0] *= al0;  acc_o[nt][1] *= al0;
            acc_o[nt][2] *= al1;  acc_o[nt][3] *= al1;
        }

        #pragma unroll
        for (int kt = 0; kt < 4; kt++) {
            uint32_t ap[4];
            ap[0] = f2h2(s[2*kt  ][0], s[2*kt  ][1]);
            ap[1] = f2h2(s[2*kt  ][2], s[2*kt  ][3]);
            ap[2] = f2h2(s[2*kt+1][0], s[2*kt+1][1]);
            ap[3] = f2h2(s[2*kt+1][2], s[2*kt+1][3]);
            #pragma unroll
            for (int p = 0; p < 4; p++) {
                uint32_t bv[2][2];
                uint32_t vd = vs + (uint32_t)((kt*16 + v_r)*ST + p*16 + v_c8)*2;
                LDSM_X4T(bv[0][0], bv[0][1], bv[1][0], bv[1][1], vd);
                mma_f16(acc_o[2*p  ], ap, bv[0]);
                mma_f16(acc_o[2*p+1], ap, bv[1]);
            }
        }
    }

    float r0 = 1.f / l0, r1 = 1.f / l1;
    #pragma unroll
    for (int nt = 0; nt < 8; nt++) {
        int c = nt*8 + 2*tg;
        *(uint32_t*)&Ob[(long)(wm+g  )*DIM + c] = f2h2(acc_o[nt][0]*r0, acc_o[nt][1]*r0);
        *(uint32_t*)&Ob[(long)(wm+g+8)*DIM + c] = f2h2(acc_o[nt][2]*r1, acc_o[nt][3]*r1);
    }
}

// ---------------- merged weight transposes (7 segments, flat grid) ----------
__global__ void prep_weights(
    const float* w0, const float* w1, const float* w2, const float* w3,
    const float* w4, const float* w5, const float* w6,
    __half* o0, __half* o1, __half* o2, __half* o3,
    __half* o4, __half* o5, __half* o6)
{
    const int gx[7]  = {96, 32, 32, 64, 32, 128, 32};
    const int off[8] = {0, 3072, 4096, 5120, 7168, 8192, 12288, 16384};
    const int ldi[7] = {3072, 1024, 1024, 2048, 1024, 4096, 1024};
    const int ldo[7] = {1024, 1024, 1024, 1024, 1024, 1024, 4096};

    int bid = blockIdx.x;
    int seg = 0;
    #pragma unroll
    for (int s = 1; s < 7; s++) if (bid >= off[s]) seg = s;
    int lt = bid - off[seg];
    int bx = lt % gx[seg], by = lt / gx[seg];

    const float* in  = (seg==0)?w0:(seg==1)?w1:(seg==2)?w2:(seg==3)?w3:(seg==4)?w4:(seg==5)?w5:w6;
    __half*      out = (seg==0)?o0:(seg==1)?o1:(seg==2)?o2:(seg==3)?o3:(seg==4)?o4:(seg==5)?o5:o6;
    int ldin = ldi[seg], ldout = ldo[seg];

    __shared__ float t[32][33];
    int r0 = by*32, c0 = bx*32;
    int x = threadIdx.x, y = threadIdx.y;
    #pragma unroll
    for (int i = 0; i < 32; i += 8) t[y+i][x] = in[(long)(r0+y+i)*ldin + c0 + x];
    __syncthreads();
    #pragma unroll
    for (int i = 0; i < 32; i += 8)
        out[(long)(c0+y+i)*ldout + r0 + x] = __float2half(t[x][y+i]);
}

// ---------------- merged fp32 -> half convert (x and ctx) ----------------
__global__ void f2h_dual(const float* __restrict__ a, __half* __restrict__ ah,
                         const float* __restrict__ b, __half* __restrict__ bh, int n4)
{
    int i = blockIdx.x*blockDim.x + threadIdx.x;
    const float* in; __half* out;
    if (i < n4) { in = a; out = ah; }
    else        { in = b; out = bh; i -= n4; if (i >= n4) return; }
    float4 v = ((const float4*)in)[i];
    ((uint32_t*)out)[2*i    ] = f2h2(v.x, v.y);
    ((uint32_t*)out)[2*i + 1] = f2h2(v.z, v.w);
}

// ---------------- fused residual add + LayerNorm ----------------
__global__ void __launch_bounds__(256) add_ln(
    const float* __restrict__ x, const float* __restrict__ a,
    const float* __restrict__ g, const float* __restrict__ b,
    float* __restrict__ y, __half* __restrict__ yh)
{
    __shared__ float red[8];
    __shared__ float bc;
    long row = blockIdx.x;
    const float* xr = x + row * DIM;
    const float* ar = a + row * DIM;
    float* yr = y + row * DIM;
    int tid = threadIdx.x, lane = tid & 31, wid = tid >> 5;

    float v[4], s = 0.f;
    #pragma unroll
    for (int i = 0; i < 4; i++) { int c = tid + i*256; v[i] = xr[c] + ar[c]; s += v[i]; }
    #pragma unroll
    for (int o = 16; o > 0; o >>= 1) s += __shfl_xor_sync(0xffffffffu, s, o);
    if (lane == 0) red[wid] = s;
    __syncthreads();
    if (tid == 0) {
        float t = 0.f;
        #pragma unroll
        for (int i = 0; i < 8; i++) t += red[i];
        bc = t * (1.0f / DIM);
    }
    __syncthreads();
    float mu = bc;

    float q = 0.f;
    #pragma unroll
    for (int i = 0; i < 4; i++) { float d = v[i] - mu; q += d * d; }
    #pragma unroll
    for (int o = 16; o > 0; o >>= 1) q += __shfl_xor_sync(0xffffffffu, q, o);
    __syncthreads();
    if (lane == 0) red[wid] = q;
    __syncthreads();
    if (tid == 0) {
        float t = 0.f;
        #pragma unroll
        for (int i = 0; i < 8; i++) t += red[i];
        bc = rsqrtf(t * (1.0f / DIM) + 1e-5f);
    }
    __syncthreads();
    float inv = bc;
    #pragma unroll
    for (int i = 0; i < 4; i++) {
        int c = tid + i*256;
        float o = (v[i] - mu) * inv * g[c] + b[c];
        yr[c] = o;
        if (yh) yh[row*DIM + c] = __float2half(o);
    }
}

// ---------------- host orchestration (two-stream graph) ----------------
extern "C" void kernel_launch(void* const* d_in, const int* in_sizes, int n_in,
                              void* d_out, int out_size)
{
    const float* x            = (const float*)d_in[0];
    const float* ctx          = (const float*)d_in[1];
    const float* c_attn_w     = (const float*)d_in[2];
    const float* c_attn_b     = (const float*)d_in[3];
    const float* self_proj_w  = (const float*)d_in[4];
    const float* self_proj_b  = (const float*)d_in[5];
    const float* q_w          = (const float*)d_in[6];
    const float* q_b          = (const float*)d_in[7];
    const float* kv_w         = (const float*)d_in[8];
    const float* kv_b         = (const float*)d_in[9];
    const float* cross_proj_w = (const float*)d_in[10];
    const float* cross_proj_b = (const float*)d_in[11];
    const float* fc_w         = (const float*)d_in[12];
    const float* fc_b         = (const float*)d_in[13];
    const float* mlp_proj_w   = (const float*)d_in[14];
    const float* mlp_proj_b   = (const float*)d_in[15];
    const float* ln1_g        = (const float*)d_in[16];
    const float* ln1_b        = (const float*)d_in[17];
    const float* ln2_g        = (const float*)d_in[18];
    const float* ln2_b        = (const float*)d_in[19];
    const float* ln3_g        = (const float*)d_in[20];
    const float* ln3_b        = (const float*)d_in[21];
    float* out = (float*)d_out;

    float *t, *x1, *x2;
    __half *qkvh, *abufh, *xh, *ctxh, *x1h, *x2h, *qh, *kvh, *hh, *wth;
    cudaGetSymbolAddress((void**)&t,     g_t);
    cudaGetSymbolAddress((void**)&x1,    g_x1);
    cudaGetSymbolAddress((void**)&x2,    g_x2);
    cudaGetSymbolAddress((void**)&qkvh,  g_qkvh);
    cudaGetSymbolAddress((void**)&abufh, g_abufh);
    cudaGetSymbolAddress((void**)&xh,    g_xh);
    cudaGetSymbolAddress((void**)&ctxh,  g_ctxh);
    cudaGetSymbolAddress((void**)&x1h,   g_x1h);
    cudaGetSymbolAddress((void**)&x2h,   g_x2h);
    cudaGetSymbolAddress((void**)&qh,    g_qh);
    cudaGetSymbolAddress((void**)&kvh,   g_kvh);
    cudaGetSymbolAddress((void**)&hh,    g_hh);
    cudaGetSymbolAddress((void**)&wth,   g_wth);

    __half* cattnT = wth;                        // [3072,1024]
    __half* selfT  = wth +  3l*1024*1024;
    __half* qT     = wth +  4l*1024*1024;
    __half* kvT    = wth +  5l*1024*1024;        // [2048,1024]
    __half* crossT = wth +  7l*1024*1024;
    __half* fcT    = wth +  8l*1024*1024;        // [4096,1024]
    __half* mlpT   = wth + 12l*1024*1024;        // [1024,4096]

    const int SMG = (128*40 + 128*40) * 3 * 2;          // 61440 B (3 stages)
    const int SMF = (64*72 + 3*(2*64*72)) * 2;          // 64512 B (Q + 3 KV stages)

    static bool init_done = false;
    static cudaStream_t s2;
    static cudaEvent_t evStart, evF, evW, evKV;
    if (!init_done) {
        cudaFuncSetAttribute(gemm_mma<EPI_BIAS, true>,      cudaFuncAttributeMaxDynamicSharedMemorySize, SMG);
        cudaFuncSetAttribute(gemm_mma<EPI_BIAS, false>,     cudaFuncAttributeMaxDynamicSharedMemorySize, SMG);
        cudaFuncSetAttribute(gemm_mma<EPI_BIAS_GELU, true>, cudaFuncAttributeMaxDynamicSharedMemorySize, SMG);
        cudaFuncSetAttribute(flash_attn, cudaFuncAttributeMaxDynamicSharedMemorySize, SMF);
        cudaStreamCreateWithFlags(&s2, cudaStreamNonBlocking);
        cudaEventCreateWithFlags(&evStart, cudaEventDisableTiming);
        cudaEventCreateWithFlags(&evF,     cudaEventDisableTiming);
        cudaEventCreateWithFlags(&evW,     cudaEventDisableTiming);
        cudaEventCreateWithFlags(&evKV,    cudaEventDisableTiming);
        init_done = true;
    }

    const int M = NB * SEQ;                  // 4096

    // ---- fork: side stream does weight prep, then the kv projection ----
    cudaEventRecord(evStart, 0);
    cudaStreamWaitEvent(s2, evStart, 0);

    // main: input converts (xh, ctxh)
    f2h_dual<<<8192, 256>>>(x, xh, ctx, ctxh, M*DIM/4);
    cudaEventRecord(evF, 0);

    // side: all weight transposes
    prep_weights<<<16384, dim3(32, 8), 0, s2>>>(
        c_attn_w, self_proj_w, q_w, kv_w, cross_proj_w, fc_w, mlp_proj_w,
        cattnT, selfT, qT, kvT, crossT, fcT, mlpT);
    cudaEventRecord(evW, s2);

    // side: kv = ctx @ kv_w + b  (needs ctxh from main + kvT local)
    cudaStreamWaitEvent(s2, evF, 0);
    gemm_mma<EPI_BIAS, true><<<dim3(16, 32), 128, SMG, s2>>>(
        ctxh, kvT, kv_b, nullptr, kvh, DIM, DIM, DIM, 2*DIM);
    cudaEventRecord(evKV, s2);

    // main waits for weights (cattnT) before qkv
    cudaStreamWaitEvent(0, evW, 0);

    // 1. qkv = x @ c_attn_w + b   (half out)
    gemm_mma<EPI_BIAS, true><<<dim3(24, 32), 128, SMG>>>(
        xh, cattnT, c_attn_b, nullptr, qkvh, DIM, DIM, DIM, 3*DIM);

    // 2-4. fused causal self-attention -> abufh
    flash_attn<<<dim3(16, NB*NHEAD), 128, SMF>>>(
        qkvh, qkvh + DIM, qkvh + 2*DIM, abufh, 3*DIM, 3*DIM, 1);

    // 5. t = a @ self_proj_w + b  (fp32 out)
    gemm_mma<EPI_BIAS, false><<<dim3(8, 32), 128, SMG>>>(
        abufh, selfT, self_proj_b, t, nullptr, DIM, DIM, DIM, DIM);

    // 6. x1 = LN(x + t)  (+ half copy)
    add_ln<<<M, 256>>>(x, t, ln1_g, ln1_b, x1, x1h);

    // 7. q = x1 @ q_w + b  (half out)
    gemm_mma<EPI_BIAS, true><<<dim3(8, 32), 128, SMG>>>(
        x1h, qT, q_b, nullptr, qh, DIM, DIM, DIM, DIM);

    // join: cross-attention needs kv from side stream
    cudaStreamWaitEvent(0, evKV, 0);

    // 9-11. fused cross-attention -> abufh
    flash_attn<<<dim3(16, NB*NHEAD), 128, SMF>>>(
        qh, kvh, kvh + DIM, abufh, DIM, 2*DIM, 0);

    // 12. t = a @ cross_proj_w + b  (fp32 out)
    gemm_mma<EPI_BIAS, false><<<dim3(8, 32), 128, SMG>>>(
        abufh, crossT, cross_proj_b, t, nullptr, DIM, DIM, DIM, DIM);

    // 13. x2 = LN(x1 + t)  (+ half copy)
    add_ln<<<M, 256>>>(x1, t, ln2_g, ln2_b, x2, x2h);

    // 14. h = gelu(x2 @ fc_w + b)  (half out)
    gemm_mma<EPI_BIAS_GELU, true><<<dim3(32, 32), 128, SMG>>>(
        x2h, fcT, fc_b, nullptr, hh, DIM, DIM, DIM, 4*DIM);

    // 15. t = h @ mlp_proj_w + b  (fp32 out)
    gemm_mma<EPI_BIAS, false><<<dim3(8, 32), 128, SMG>>>(
        hh, mlpT, mlp_proj_b, t, nullptr, 4*DIM, 4*DIM, 4*DIM, DIM);

    // 16. out = LN(x2 + t)
    add_ln<<<M, 256>>>(x2, t, ln3_g, ln3_b, out, nullptr);
}